// round 8
// baseline (speedup 1.0000x reference)
#include <cuda_runtime.h>
#include <cuda_fp16.h>
#include <cstdint>

// ---------------------------------------------------------------------------
// Implicit GEMM for segmented Conv4d (3x3 over (S,t), pointwise h,w), fp16
// tensor cores. EXPERIMENT: f16-accumulate mma (possible 2x issue rate vs
// f32-acc) with per-iteration (K=64) fold into persistent f32 accumulators.
//   x: (8,1024,4,14,14) fp32   W: (1024,1024,3,3) fp32   out: like x
//   Xt row r = ((b'*6+s')*6+t')*196 + p, ci contiguous (pad cells zeroed).
//   q = b*784 + t*196 + p;  rbase(q) = b'*7056 + s*1176 + t*196 + p
//   tap (ks,kt) adds ks*1176 + kt*196.  y[q,co] = sum Wt[tap][co][.]*Xt[row][.] + x
// CTA 128(co) x 112(q), 4 warps (2x2, warp tile 64x56), K-chunk 64, 144 iters,
// 3-stage cp.async ring, 2 CTAs/SM, grid 8 x 56.
// ---------------------------------------------------------------------------
#define CIN      1024
#define COUT     1024
#define XTROWS   14112
#define MT       128
#define NT       112
#define MTILES   8
#define NTILES   56
#define ITERS    144            // 9 taps * 16 ci-chunks of 64
#define STAGES   3
#define ROWB     144            // 64 halves (128B) + 16B pad
#define A_BYTES  (MT * ROWB)    // 18432
#define B_BYTES  (NT * ROWB)    // 16128
#define STAGE_BYTES (A_BYTES + B_BYTES)  // 34560
#define OFF_STAGE 1024
#define SMEM_MAIN (OFF_STAGE + STAGES * STAGE_BYTES)   // 104704

__device__ __half g_Xt[XTROWS * CIN];    // 28.9 MB padded transposed input
__device__ __half g_Wt[9 * COUT * CIN];  // 18.9 MB per-tap K-major weights

// ----------------------------- helpers -------------------------------------
__device__ __forceinline__ unsigned s2u(const void* p) {
    unsigned a;
    asm("{ .reg .u64 t; cvta.to.shared.u64 t, %1; cvt.u32.u64 %0, t; }" : "=r"(a) : "l"(p));
    return a;
}
__device__ __forceinline__ void cp16(unsigned s, const void* g) {
    asm volatile("cp.async.cg.shared.global [%0], [%1], 16;" :: "r"(s), "l"(g) : "memory");
}
__device__ __forceinline__ void cp_commit() {
    asm volatile("cp.async.commit_group;" ::: "memory");
}
__device__ __forceinline__ void cp_wait1() {
    asm volatile("cp.async.wait_group 1;" ::: "memory");
}
__device__ __forceinline__ void ldsm4(unsigned* d, unsigned a) {
    asm volatile("ldmatrix.sync.aligned.m8n8.x4.shared.b16 {%0,%1,%2,%3}, [%4];"
                 : "=r"(d[0]), "=r"(d[1]), "=r"(d[2]), "=r"(d[3]) : "r"(a));
}
__device__ __forceinline__ void ldsm2(unsigned* d, unsigned a) {
    asm volatile("ldmatrix.sync.aligned.m8n8.x2.shared.b16 {%0,%1}, [%2];"
                 : "=r"(d[0]), "=r"(d[1]) : "r"(a));
}
// f16-accumulate variant: D,C are 2 regs of half2
__device__ __forceinline__ void mma_f16h(unsigned* c, const unsigned* a, const unsigned* b) {
    asm volatile(
        "mma.sync.aligned.m16n8k16.row.col.f16.f16.f16.f16 "
        "{%0,%1}, {%2,%3,%4,%5}, {%6,%7}, {%0,%1};"
        : "+r"(c[0]), "+r"(c[1])
        : "r"(a[0]), "r"(a[1]), "r"(a[2]), "r"(a[3]), "r"(b[0]), "r"(b[1]));
}

// ----------------------------- prep kernels --------------------------------
__global__ void prep_x(const float* __restrict__ x) {
    __shared__ float sm[32 * 197];
    int cell = blockIdx.x;              // (b'*6 + s')*6 + t'
    int ci0 = blockIdx.y * 32;
    int bp = cell / 36;
    int sp = (cell / 6) % 6;
    int tp = cell % 6;
    int rbase = cell * 196;
    int tid = threadIdx.x;
    bool pad = (sp == 0) | (sp == 5) | (tp == 0) | (tp == 5);
    if (!pad) {
        int b = bp * 4 + (sp - 1);
        int t = tp - 1;
        long xbase = (long)(b * CIN + ci0) * 784 + t * 196;
        for (int l = tid; l < 32 * 196; l += 256) {
            int i = l / 196, p = l - i * 196;
            sm[i * 197 + p] = x[xbase + (long)i * 784 + p];
        }
        __syncthreads();
        for (int l = tid; l < 196 * 16; l += 256) {
            int p = l >> 4, j = l & 15;
            __half2 v = __floats2half2_rn(sm[(2 * j) * 197 + p], sm[(2 * j + 1) * 197 + p]);
            ((__half2*)&g_Xt[(long)(rbase + p) * CIN + ci0])[j] = v;
        }
    } else {
        __half2 z = __floats2half2_rn(0.0f, 0.0f);
        for (int l = tid; l < 196 * 16; l += 256) {
            int p = l >> 4, j = l & 15;
            ((__half2*)&g_Xt[(long)(rbase + p) * CIN + ci0])[j] = z;
        }
    }
}

__global__ void prep_w(const float* __restrict__ W) {
    long t = (long)blockIdx.x * 256 + threadIdx.x;   // co*1024 + ci
    const float* p = W + t * 9;
    float v[9];
#pragma unroll
    for (int k = 0; k < 9; k++) v[k] = p[k];
#pragma unroll
    for (int k = 0; k < 9; k++) g_Wt[(long)k * (COUT * CIN) + t] = __float2half_rn(v[k]);
}

// ----------------------------- main GEMM -----------------------------------
__global__ void __launch_bounds__(128, 2) conv_main(const float* __restrict__ x,
                                                    float* __restrict__ out) {
    extern __shared__ __align__(16) char smem[];
    const int tid = threadIdx.x, wid = tid >> 5, lid = tid & 31;
    const int gid = lid >> 2, tig = lid & 3;
    const int mtile = blockIdx.x, ntile = blockIdx.y;
    const int wm = (wid >> 1) * 64;     // warp m offset {0,64}
    const int wn = (wid & 1) * 56;      // warp n offset {0,56}

    __shared__ int rbase_s[NT];
    if (tid < NT) {
        int q = ntile * NT + tid;
        int b = q / 784;
        int rem = q - b * 784;
        int t = rem / 196;
        int p = rem - t * 196;
        rbase_s[tid] = (b >> 2) * 7056 + (b & 3) * 1176 + t * 196 + p;
    }
    __syncthreads();

    // producer cp.async addresses: A 1024 chunks (8/thr), B 896 chunks (7/thr)
    unsigned gA[8], sA[8], gB[7], sB[7];
#pragma unroll
    for (int k = 0; k < 8; k++) {
        int c = tid + 128 * k;
        int row = c >> 3, j = c & 7;             // 8 x 16B = 128B (64 halves)
        gA[k] = (unsigned)((mtile * MT + row) * 2048 + j * 16);
        sA[k] = (unsigned)(OFF_STAGE + row * ROWB + j * 16);
    }
#pragma unroll
    for (int k = 0; k < 7; k++) {
        int c = tid + 128 * k;
        int n = c >> 3, j = c & 7;
        gB[k] = (unsigned)(rbase_s[n] * 2048 + j * 16);
        sB[k] = (unsigned)(OFF_STAGE + A_BYTES + n * ROWB + j * 16);
    }
    const unsigned sb = s2u(smem);
    const char* WtB = (const char*)g_Wt;
    const char* XtB = (const char*)g_Xt;

    // ldmatrix per-lane base addresses
    const int lm = lid >> 3, lr = lid & 7;
    const unsigned aBase = sb + OFF_STAGE +
        (unsigned)((wm + (lm & 1) * 8 + lr) * ROWB + (lm >> 1) * 16);
    const unsigned bBase = sb + OFF_STAGE + A_BYTES +
        (unsigned)((wn + (lm >> 1) * 8 + lr) * ROWB + (lm & 1) * 16);
    const unsigned b6Base = sb + OFF_STAGE + A_BYTES +
        (unsigned)((wn + 48 + lr) * ROWB + (lm & 1) * 16);

    float acc[4][7][4];
#pragma unroll
    for (int i = 0; i < 4; i++)
#pragma unroll
        for (int j = 0; j < 7; j++)
#pragma unroll
            for (int k = 0; k < 4; k++) acc[i][j][k] = 0.0f;

    auto issue = [&](int it, int slot) {
        if (it < ITERS) {
            int tap = it >> 4, kc = it & 15;
            int ks = tap / 3, kt = tap - ks * 3;
            unsigned soA = (unsigned)tap * 2097152u + (unsigned)kc * 128u;
            unsigned soB = (unsigned)(ks * 1176 + kt * 196) * 2048u + (unsigned)kc * 128u;
            unsigned st = (unsigned)slot * STAGE_BYTES;
#pragma unroll
            for (int k = 0; k < 8; k++) cp16(sb + sA[k] + st, WtB + gA[k] + soA);
#pragma unroll
            for (int k = 0; k < 7; k++) cp16(sb + sB[k] + st, XtB + gB[k] + soB);
        }
        cp_commit();
    };

    issue(0, 0);
    issue(1, 1);

    int cs = 0, ps = 2;
#pragma unroll 1
    for (int it = 0; it < ITERS; ++it) {
        cp_wait1();
        __syncthreads();
        issue(it + 2, ps);
        ps = (ps == STAGES - 1) ? 0 : ps + 1;
        const unsigned stg = (unsigned)cs * STAGE_BYTES;
        cs = (cs == STAGES - 1) ? 0 : cs + 1;

        // per-iteration f16 accumulators (folded into f32 at iter end)
        unsigned hacc[4][7][2];
#pragma unroll
        for (int i = 0; i < 4; i++)
#pragma unroll
            for (int j = 0; j < 7; j++) { hacc[i][j][0] = 0u; hacc[i][j][1] = 0u; }

#pragma unroll
        for (int kk = 0; kk < 4; kk++) {       // 4 x K16 = 64 halves
            unsigned a[4][4], b[7][2];
#pragma unroll
            for (int im = 0; im < 4; im++)
                ldsm4(a[im], aBase + stg + (unsigned)(im * (16 * ROWB) + kk * 32));
#pragma unroll
            for (int p = 0; p < 3; p++) {
                unsigned d[4];
                ldsm4(d, bBase + stg + (unsigned)(p * (16 * ROWB) + kk * 32));
                b[2 * p][0] = d[0]; b[2 * p][1] = d[1];
                b[2 * p + 1][0] = d[2]; b[2 * p + 1][1] = d[3];
            }
            ldsm2(b[6], b6Base + stg + (unsigned)(kk * 32));
#pragma unroll
            for (int im = 0; im < 4; im++)
#pragma unroll
                for (int in = 0; in < 7; in++) mma_f16h(hacc[im][in], a[im], b[in]);
        }

        // fold f16 partials into f32 accumulators
#pragma unroll
        for (int im = 0; im < 4; im++)
#pragma unroll
            for (int in = 0; in < 7; in++) {
                float2 f0 = __half22float2(*(__half2*)&hacc[im][in][0]);
                float2 f1 = __half22float2(*(__half2*)&hacc[im][in][1]);
                acc[im][in][0] += f0.x;
                acc[im][in][1] += f0.y;
                acc[im][in][2] += f1.x;
                acc[im][in][3] += f1.y;
            }
    }

    // ------------------------- epilogue: residual add -----------------------
#pragma unroll
    for (int im = 0; im < 4; im++) {
        int m0 = mtile * MT + wm + im * 16 + gid;       // co row (and +8)
#pragma unroll
        for (int in = 0; in < 7; in++) {
            int q = ntile * NT + wn + in * 8 + 2 * tig; // even start => pair in-bounds
            int b = q / 784;
            int rem = q - b * 784;
            int off0 = b * 802816 + m0 * 784 + rem;
            int off1 = off0 + 8 * 784;
            float2 x0 = *(const float2*)(x + off0);
            float2 x1 = *(const float2*)(x + off1);
            float2 o0 = make_float2(acc[im][in][0] + x0.x, acc[im][in][1] + x0.y);
            float2 o1 = make_float2(acc[im][in][2] + x1.x, acc[im][in][3] + x1.y);
            *(float2*)(out + off0) = o0;
            *(float2*)(out + off1) = o1;
        }
    }
}

// ----------------------------- launch --------------------------------------
extern "C" void kernel_launch(void* const* d_in, const int* in_sizes, int n_in,
                              void* d_out, int out_size) {
    const float* x = (const float*)d_in[0];
    const float* W = (const float*)d_in[1];
    if (n_in >= 2 && in_sizes[0] != 8 * 1024 * 4 * 14 * 14) {  // robustness
        x = (const float*)d_in[1];
        W = (const float*)d_in[0];
    }
    float* out = (float*)d_out;

    prep_w<<<4096, 256>>>(W);
    dim3 gx(72, 32);
    prep_x<<<gx, 256>>>(x);

    cudaFuncSetAttribute(conv_main, cudaFuncAttributeMaxDynamicSharedMemorySize, SMEM_MAIN);
    dim3 grid(MTILES, NTILES);
    conv_main<<<grid, 128, SMEM_MAIN>>>(x, out);
}

// round 9
// speedup vs baseline: 1.6623x; 1.6623x over previous
#include <cuda_runtime.h>
#include <cuda_fp16.h>
#include <cstdint>

// ---------------------------------------------------------------------------
// Winograd F(2x2,3x3) implicit GEMM for segmented Conv4d.
//   x: (8,1024,4,14,14) fp32   W: (1024,1024,3,3) fp32   out: like x
// Per (b' in [0,2), p in [0,196)): 3x3 correlation over padded 6x6 (s',t')
// grid with 1024 ci -> 1024 co. Winograd: 16 uv-planes of pointwise GEMM
//   M~[uv][co][tile] = sum_ci U[uv][co][ci] * V[uv][tile][ci]
// tile = (b'*196+p)*4 + i*2+j  (2x2 output tile grid),  N = 1568, K = 1024.
// Then y(2x2 per tile) = A^T m A + x.
// U = G g G^T (fp16), V = B^T d B (fp16, transform in fp32, round once).
// GEMM: cp.async + ldmatrix + mma.sync.m16n8k16.f16 (f32 acc), CTA 128x112,
// 4 warps (2x2), 3-stage ring, grid (8,14,4): 4 uv per CTA, flush every 16 it.
// ---------------------------------------------------------------------------
#define CIN      1024
#define COUT     1024
#define NTT      1568           // tiles total
#define MT       128
#define NT       112
#define ITERS    64             // 4 uv * 16 ci-chunks of 64
#define STAGES   3
#define ROWB     144            // 64 halves (128B) + 16B pad
#define A_BYTES  (MT * ROWB)    // 18432
#define B_BYTES  (NT * ROWB)    // 16128
#define STAGE_BYTES (A_BYTES + B_BYTES)  // 34560
#define OFF_STAGE 1024
#define SMEM_MAIN (OFF_STAGE + STAGES * STAGE_BYTES)   // 104704
#define UPLANE   (1024 * 1024)          // elems per U plane
#define VPLANE   (NTT * 1024)           // elems per V plane
#define MPLANE   (1024 * NTT)           // elems per M plane

__device__ float  g_Xt[14112 * 1024];     // 57.8 MB padded (s',t')-grid input, fp32
__device__ __half g_U[16 * UPLANE];       // 33.5 MB transformed weights
__device__ __half g_V[16 * VPLANE];       // 51.4 MB transformed inputs
__device__ float  g_M[16 * MPLANE];       // 102.8 MB GEMM outputs (m values)

// ----------------------------- helpers -------------------------------------
__device__ __forceinline__ unsigned s2u(const void* p) {
    unsigned a;
    asm("{ .reg .u64 t; cvta.to.shared.u64 t, %1; cvt.u32.u64 %0, t; }" : "=r"(a) : "l"(p));
    return a;
}
__device__ __forceinline__ void cp16(unsigned s, const void* g) {
    asm volatile("cp.async.cg.shared.global [%0], [%1], 16;" :: "r"(s), "l"(g) : "memory");
}
__device__ __forceinline__ void cp_commit() {
    asm volatile("cp.async.commit_group;" ::: "memory");
}
__device__ __forceinline__ void cp_wait1() {
    asm volatile("cp.async.wait_group 1;" ::: "memory");
}
__device__ __forceinline__ void ldsm4(unsigned* d, unsigned a) {
    asm volatile("ldmatrix.sync.aligned.m8n8.x4.shared.b16 {%0,%1,%2,%3}, [%4];"
                 : "=r"(d[0]), "=r"(d[1]), "=r"(d[2]), "=r"(d[3]) : "r"(a));
}
__device__ __forceinline__ void ldsm2(unsigned* d, unsigned a) {
    asm volatile("ldmatrix.sync.aligned.m8n8.x2.shared.b16 {%0,%1}, [%2];"
                 : "=r"(d[0]), "=r"(d[1]) : "r"(a));
}
__device__ __forceinline__ void mma_f16(float* c, const unsigned* a, const unsigned* b) {
    asm volatile(
        "mma.sync.aligned.m16n8k16.row.col.f32.f16.f16.f32 "
        "{%0,%1,%2,%3}, {%4,%5,%6,%7}, {%8,%9}, {%0,%1,%2,%3};"
        : "+f"(c[0]), "+f"(c[1]), "+f"(c[2]), "+f"(c[3])
        : "r"(a[0]), "r"(a[1]), "r"(a[2]), "r"(a[3]), "r"(b[0]), "r"(b[1]));
}

// ----------------------------- prep: pad+transpose x (fp32) ----------------
__global__ void prep_x(const float* __restrict__ x) {
    __shared__ float sm[32 * 197];
    int cell = blockIdx.x;              // (b'*6 + s')*6 + t'
    int ci0 = blockIdx.y * 32;
    int bp = cell / 36;
    int sp = (cell / 6) % 6;
    int tp = cell % 6;
    int rbase = cell * 196;
    int tid = threadIdx.x;
    bool pad = (sp == 0) | (sp == 5) | (tp == 0) | (tp == 5);
    if (!pad) {
        int b = bp * 4 + (sp - 1);
        int t = tp - 1;
        long xbase = (long)(b * CIN + ci0) * 784 + t * 196;
        for (int l = tid; l < 32 * 196; l += 256) {
            int i = l / 196, p = l - i * 196;
            sm[i * 197 + p] = x[xbase + (long)i * 784 + p];
        }
        __syncthreads();
        for (int l = tid; l < 32 * 196; l += 256) {
            int p = l >> 5, i = l & 31;
            g_Xt[(long)(rbase + p) * CIN + ci0 + i] = sm[i * 197 + p];
        }
    } else {
        for (int l = tid; l < 32 * 196; l += 256) {
            int p = l >> 5, i = l & 31;
            g_Xt[(long)(rbase + p) * CIN + ci0 + i] = 0.0f;
        }
    }
}

// ----------------------------- weight transform U = G g G^T ----------------
__global__ void prep_w2(const float* __restrict__ W) {
    long t = (long)blockIdx.x * 256 + threadIdx.x;   // co*1024 + ci
    const float* pw = W + t * 9;
    float g[3][3];
#pragma unroll
    for (int a = 0; a < 3; a++)
#pragma unroll
        for (int b = 0; b < 3; b++) g[a][b] = pw[a * 3 + b];
    float u[4][3];
#pragma unroll
    for (int b = 0; b < 3; b++) {
        u[0][b] = g[0][b];
        u[1][b] = 0.5f * (g[0][b] + g[1][b] + g[2][b]);
        u[2][b] = 0.5f * (g[0][b] - g[1][b] + g[2][b]);
        u[3][b] = g[2][b];
    }
#pragma unroll
    for (int a = 0; a < 4; a++) {
        float U0 = u[a][0];
        float U1 = 0.5f * (u[a][0] + u[a][1] + u[a][2]);
        float U2 = 0.5f * (u[a][0] - u[a][1] + u[a][2]);
        float U3 = u[a][2];
        g_U[(long)(a * 4 + 0) * UPLANE + t] = __float2half_rn(U0);
        g_U[(long)(a * 4 + 1) * UPLANE + t] = __float2half_rn(U1);
        g_U[(long)(a * 4 + 2) * UPLANE + t] = __float2half_rn(U2);
        g_U[(long)(a * 4 + 3) * UPLANE + t] = __float2half_rn(U3);
    }
}

// ----------------------------- input transform V = B^T d B ------------------
__global__ void prep_x2() {
    int bpp = blockIdx.x;                 // b'*196 + p
    int ci = blockIdx.y * 128 + threadIdx.x;
    int bp = bpp / 196, p = bpp - bp * 196;
    float d[6][6];
#pragma unroll
    for (int s = 0; s < 6; s++)
#pragma unroll
        for (int t = 0; t < 6; t++)
            d[s][t] = g_Xt[(long)(((bp * 6 + s) * 6 + t) * 196 + p) * 1024 + ci];
#pragma unroll
    for (int i = 0; i < 2; i++)
#pragma unroll
        for (int j = 0; j < 2; j++) {
            float v[4][4], V[4][4];
#pragma unroll
            for (int b = 0; b < 4; b++) {
                float e0 = d[2 * i + 0][2 * j + b];
                float e1 = d[2 * i + 1][2 * j + b];
                float e2 = d[2 * i + 2][2 * j + b];
                float e3 = d[2 * i + 3][2 * j + b];
                v[0][b] = e0 - e2;
                v[1][b] = e1 + e2;
                v[2][b] = e2 - e1;
                v[3][b] = e1 - e3;
            }
#pragma unroll
            for (int u = 0; u < 4; u++) {
                V[u][0] = v[u][0] - v[u][2];
                V[u][1] = v[u][1] + v[u][2];
                V[u][2] = v[u][2] - v[u][1];
                V[u][3] = v[u][1] - v[u][3];
            }
            long tile = (long)(bpp * 4 + i * 2 + j);
#pragma unroll
            for (int u = 0; u < 4; u++)
#pragma unroll
                for (int w = 0; w < 4; w++)
                    g_V[(long)(u * 4 + w) * VPLANE + tile * 1024 + ci] =
                        __float2half_rn(V[u][w]);
        }
}

// ----------------------------- main GEMM (16 uv planes) ---------------------
__global__ void __launch_bounds__(128, 2) conv_main() {
    extern __shared__ __align__(16) char smem[];
    const int tid = threadIdx.x, wid = tid >> 5, lid = tid & 31;
    const int gid = lid >> 2, tig = lid & 3;
    const int mtile = blockIdx.x, ntile = blockIdx.y;
    const int uvg = blockIdx.z * 4;
    const int wm = (wid >> 1) * 64;     // warp m offset {0,64}
    const int wn = (wid & 1) * 56;      // warp n offset {0,56}

    // producer cp.async addresses: A 1024 chunks (8/thr), B 896 chunks (7/thr)
    unsigned gA[8], sA[8], gB[7], sB[7];
#pragma unroll
    for (int k = 0; k < 8; k++) {
        int c = tid + 128 * k;
        int row = c >> 3, j = c & 7;             // 8 x 16B = 128B (64 halves)
        gA[k] = (unsigned)((mtile * MT + row) * 2048 + j * 16);
        sA[k] = (unsigned)(OFF_STAGE + row * ROWB + j * 16);
    }
#pragma unroll
    for (int k = 0; k < 7; k++) {
        int c = tid + 128 * k;
        int n = c >> 3, j = c & 7;
        gB[k] = (unsigned)((ntile * NT + n) * 2048 + j * 16);
        sB[k] = (unsigned)(OFF_STAGE + A_BYTES + n * ROWB + j * 16);
    }
    const unsigned sb = s2u(smem);
    const char* UB = (const char*)g_U;
    const char* VB = (const char*)g_V;

    // ldmatrix per-lane base addresses
    const int lm = lid >> 3, lr = lid & 7;
    const unsigned aBase = sb + OFF_STAGE +
        (unsigned)((wm + (lm & 1) * 8 + lr) * ROWB + (lm >> 1) * 16);
    const unsigned bBase = sb + OFF_STAGE + A_BYTES +
        (unsigned)((wn + (lm >> 1) * 8 + lr) * ROWB + (lm & 1) * 16);
    const unsigned b6Base = sb + OFF_STAGE + A_BYTES +
        (unsigned)((wn + 48 + lr) * ROWB + (lm & 1) * 16);

    float acc[4][7][4];
#pragma unroll
    for (int i = 0; i < 4; i++)
#pragma unroll
        for (int j = 0; j < 7; j++)
#pragma unroll
            for (int k = 0; k < 4; k++) acc[i][j][k] = 0.0f;

    auto issue = [&](int it, int slot) {
        if (it < ITERS) {
            int uv = uvg + (it >> 4), kc = it & 15;
            unsigned soA = (unsigned)uv * (UPLANE * 2u) + (unsigned)kc * 128u;
            unsigned soB = (unsigned)uv * (VPLANE * 2u) + (unsigned)kc * 128u;
            unsigned st = (unsigned)slot * STAGE_BYTES;
#pragma unroll
            for (int k = 0; k < 8; k++) cp16(sb + sA[k] + st, UB + gA[k] + soA);
#pragma unroll
            for (int k = 0; k < 7; k++) cp16(sb + sB[k] + st, VB + gB[k] + soB);
        }
        cp_commit();
    };

    issue(0, 0);
    issue(1, 1);

    int cs = 0, ps = 2;
#pragma unroll 1
    for (int it = 0; it < ITERS; ++it) {
        cp_wait1();
        __syncthreads();
        issue(it + 2, ps);
        ps = (ps == STAGES - 1) ? 0 : ps + 1;
        const unsigned stg = (unsigned)cs * STAGE_BYTES;
        cs = (cs == STAGES - 1) ? 0 : cs + 1;
#pragma unroll
        for (int kk = 0; kk < 4; kk++) {       // 4 x K16 = 64 halves
            unsigned a[4][4], b[7][2];
#pragma unroll
            for (int im = 0; im < 4; im++)
                ldsm4(a[im], aBase + stg + (unsigned)(im * (16 * ROWB) + kk * 32));
#pragma unroll
            for (int p = 0; p < 3; p++) {
                unsigned d[4];
                ldsm4(d, bBase + stg + (unsigned)(p * (16 * ROWB) + kk * 32));
                b[2 * p][0] = d[0]; b[2 * p][1] = d[1];
                b[2 * p + 1][0] = d[2]; b[2 * p + 1][1] = d[3];
            }
            ldsm2(b[6], b6Base + stg + (unsigned)(kk * 32));
#pragma unroll
            for (int im = 0; im < 4; im++)
#pragma unroll
                for (int in = 0; in < 7; in++) mma_f16(acc[im][in], a[im], b[in]);
        }

        if ((it & 15) == 15) {                  // flush this uv's result
            int uv = uvg + (it >> 4);
            float* Mp = g_M + (long)uv * MPLANE;
#pragma unroll
            for (int im = 0; im < 4; im++) {
                int m0 = mtile * MT + wm + im * 16 + gid;
#pragma unroll
                for (int in = 0; in < 7; in++) {
                    int n0 = ntile * NT + wn + in * 8 + 2 * tig;
                    *(float2*)(Mp + m0 * NTT + n0) =
                        make_float2(acc[im][in][0], acc[im][in][1]);
                    *(float2*)(Mp + (m0 + 8) * NTT + n0) =
                        make_float2(acc[im][in][2], acc[im][in][3]);
                    acc[im][in][0] = 0.0f; acc[im][in][1] = 0.0f;
                    acc[im][in][2] = 0.0f; acc[im][in][3] = 0.0f;
                }
            }
        }
    }
}

// ----------------------------- output transform + residual ------------------
__global__ void __launch_bounds__(224) wino_out(const float* __restrict__ x,
                                                float* __restrict__ out) {
    extern __shared__ float sm[];               // [16][784]
    const int co = blockIdx.x, bp = blockIdx.y;
    const int tid = threadIdx.x;
    for (int i = tid; i < 16 * 196; i += 224) {
        int uv = i / 196, w4 = i - uv * 196;
        ((float4*)sm)[uv * 196 + w4] =
            *(const float4*)(g_M + (long)uv * MPLANE + (long)co * NTT + bp * 784 + w4 * 4);
    }
    __syncthreads();
    if (tid < 196) {
        const int p = tid;
        float4 mv[16];
#pragma unroll
        for (int uv = 0; uv < 16; uv++) mv[uv] = ((float4*)sm)[uv * 196 + p];
        const float* mvf = (const float*)mv;    // mvf[uv*4 + ij]
#pragma unroll
        for (int i = 0; i < 2; i++)
#pragma unroll
            for (int j = 0; j < 2; j++) {
                int ij = i * 2 + j;
                float m[4][4];
#pragma unroll
                for (int u = 0; u < 4; u++)
#pragma unroll
                    for (int v = 0; v < 4; v++) m[u][v] = mvf[(u * 4 + v) * 4 + ij];
                float z0[4], z1[4];
#pragma unroll
                for (int v = 0; v < 4; v++) {
                    z0[v] = m[0][v] + m[1][v] + m[2][v];
                    z1[v] = m[1][v] - m[2][v] - m[3][v];
                }
                float Y[2][2];
                Y[0][0] = z0[0] + z0[1] + z0[2];
                Y[0][1] = z0[1] - z0[2] - z0[3];
                Y[1][0] = z1[0] + z1[1] + z1[2];
                Y[1][1] = z1[1] - z1[2] - z1[3];
#pragma unroll
                for (int r = 0; r < 2; r++)
#pragma unroll
                    for (int c = 0; c < 2; c++) {
                        int s = 2 * i + r, t = 2 * j + c;
                        long off = (long)((bp * 4 + s) * 1024 + co) * 784 + t * 196 + p;
                        out[off] = Y[r][c] + x[off];
                    }
            }
    }
}

// ----------------------------- launch --------------------------------------
extern "C" void kernel_launch(void* const* d_in, const int* in_sizes, int n_in,
                              void* d_out, int out_size) {
    const float* x = (const float*)d_in[0];
    const float* W = (const float*)d_in[1];
    if (n_in >= 2 && in_sizes[0] != 8 * 1024 * 4 * 14 * 14) {  // robustness
        x = (const float*)d_in[1];
        W = (const float*)d_in[0];
    }
    float* out = (float*)d_out;

    dim3 gx(72, 32);
    prep_x<<<gx, 256>>>(x);
    prep_w2<<<4096, 256>>>(W);
    dim3 gx2(392, 8);
    prep_x2<<<gx2, 128>>>();

    cudaFuncSetAttribute(conv_main, cudaFuncAttributeMaxDynamicSharedMemorySize, SMEM_MAIN);
    dim3 grid(8, 14, 4);
    conv_main<<<grid, 128, SMEM_MAIN>>>();

    cudaFuncSetAttribute(wino_out, cudaFuncAttributeMaxDynamicSharedMemorySize, 50176);
    dim3 go(1024, 2);
    wino_out<<<go, 224, 50176>>>(x, out);
}